// round 6
// baseline (speedup 1.0000x reference)
#include <cuda_runtime.h>

// out[b,o,d,h,w] = bias[o] + sum_{i=d-2..d+2 in [0,10)} sum_{kh,kw}
//                    x[b,i,h+kh-2,w+kw-2] * W[o,i,i-d+2,kh,kw]
//
// Inputs: x[32,10,128,128] f32, W[10,10,5,5,5] f32, b[10] f32
// Output: [32,10,10,128,128] f32
//
// R6: persistent scheduling. 888 CTAs (=148 SMs x 6 slots) each process a
// contiguous range of (tile, d) jobs (10240 total, ~11.5 each, 4% remainder
// imbalance) instead of 1024 big CTAs in 1.15 waves. Consecutive jobs share
// the x tile, so xs reloads ~2x per CTA. Inner FFMA2 loop identical to R5.

#define NB 32
#define NC 10
#define HW 128

#define NCTAS   888
#define NJOBS   10240           // 1024 tiles * 10 depths

typedef unsigned long long u64;

#define FMA2(d_, a_, b_, c_) \
    asm("fma.rn.f32x2 %0, %1, %2, %3;" : "=l"(d_) : "l"(a_), "l"(b_), "l"(c_))
#define PACK2(out_, lo_, hi_) \
    asm("mov.b64 %0, {%1, %2};" : "=l"(out_) : "f"(lo_), "f"(hi_))
#define UNPACK2(lo_, hi_, in_) \
    asm("mov.b64 {%0, %1}, %2;" : "=f"(lo_), "=f"(hi_) : "l"(in_))

// Repacked weights: [d][ip][kh][kw][o], zero where i=d+ip-2 out of range.
__device__ float g_Wr[10 * 5 * 5 * 5 * 10];

__global__ void repack_kernel(const float* __restrict__ W) {
    int idx = blockIdx.x * blockDim.x + threadIdx.x;
    if (idx >= 12500) return;
    int o    = idx % 10;
    int rest = idx / 10;
    int kw = rest % 5; rest /= 5;
    int kh = rest % 5; rest /= 5;
    int ip = rest % 5;
    int d  = rest / 5;
    int i = d + ip - 2;
    float v = 0.0f;
    if (i >= 0 && i < 10)
        v = W[o * 1250 + i * 125 + ip * 25 + kh * 5 + kw];
    g_Wr[idx] = v;
}

// SMEM: xs 10ch x 20rows x pitch37 | ws 1250 | bs 10
#define XS_FLOATS (10 * 20 * 37)            // 7400
#define WSLICE 1250
#define SMEM_FLOATS (XS_FLOATS + WSLICE + 10)   // 8660 fl = 34640 B

__global__ __launch_bounds__(128, 6) void conv_main(
    const float* __restrict__ x,
    const float* __restrict__ bias,
    float* __restrict__ out)
{
    extern __shared__ float smem[];
    float* xs = smem;
    float* ws = smem + XS_FLOATS;      // byte off 29600, 8B aligned
    float* bs = ws + WSLICE;           // byte off 34600, 8B aligned

    const int tid = threadIdx.x;
    const int cta = blockIdx.x;

    // contiguous job range: q=11, r=472  (NJOBS = NCTAS*11 + 472)
    const int q = NJOBS / NCTAS;
    const int r = NJOBS % NCTAS;
    const int extra = (cta < r) ? cta : r;
    int job = cta * q + extra;
    const int jobEnd = job + q + (cta < r ? 1 : 0);

    if (tid < 10) bs[tid] = bias[tid];   // ordered by first in-loop barrier

    const int hh = tid >> 3;
    const int ww = (tid & 7) << 2;

    int curTile = -1;
    const float* xb = x;     // updated on tile change
    float* outp = out;

    for (; job < jobEnd; ++job) {
        const int d  = job % 10;
        const int tj = job / 10;

        // ---- tile change: reload xs (prev compute ordered by trailing sync) ----
        if (tj != curTile) {
            curTile = tj;
            const int b  = tj >> 5;
            const int t  = tj & 31;
            const int h0 = (t >> 2) << 4;     // 16-row tiles
            const int w0 = (t & 3) << 5;      // 32-col tiles
            xb = x + b * (NC * HW * HW);
            outp = out + b * (100 * HW * HW) + (h0 + hh) * HW + (w0 + ww);

            for (int idx = tid; idx < 10 * 20 * 36; idx += 128) {
                int c   = idx / 720;
                int rem = idx - c * 720;
                int rr_ = rem / 36;
                int col = rem - rr_ * 36;
                int gh = h0 + rr_ - 2;
                int gw = w0 + col - 2;
                float v = 0.0f;
                if ((unsigned)gh < 128u && (unsigned)gw < 128u)
                    v = __ldg(xb + c * (HW * HW) + gh * HW + gw);
                xs[(c * 20 + rr_) * 37 + col] = v;
            }
        }

        // ---- stage this d's weight slice (L1/L2-hot, shared by all CTAs) ----
        {
            const float* src = g_Wr + d * WSLICE;
            for (int idx = tid; idx < WSLICE; idx += 128)
                ws[idx] = __ldg(src + idx);
        }
        __syncthreads();

        u64 acc[5][4];
        {
            const u64* b2 = (const u64*)bs;
            #pragma unroll
            for (int o2 = 0; o2 < 5; ++o2) {
                u64 bv = b2[o2];
                #pragma unroll
                for (int p = 0; p < 4; ++p) acc[o2][p] = bv;
            }
        }

        const int iLo = (d > 2) ? d - 2 : 0;
        const int iHi = (d < 7) ? d + 2 : 9;

        for (int i = iLo; i <= iHi; ++i) {
            const int ip = i - d + 2;
            const float* wbase = ws + ip * 250;           // 5kh x 5kw x 10o
            const float* xbase = xs + (i * 20 + hh) * 37 + ww;

            #pragma unroll
            for (int kh = 0; kh < 5; ++kh) {
                const float* xr = xbase + kh * 37;
                float rv[8];
                #pragma unroll
                for (int tt = 0; tt < 8; ++tt) rv[tt] = xr[tt];
                u64 rr[8];
                #pragma unroll
                for (int tt = 0; tt < 8; ++tt) PACK2(rr[tt], rv[tt], rv[tt]);

                const u64* wk2 = (const u64*)(wbase + kh * 50);   // 8B aligned
                #pragma unroll
                for (int kw = 0; kw < 5; ++kw) {
                    u64 w[5];
                    #pragma unroll
                    for (int o2 = 0; o2 < 5; ++o2) w[o2] = wk2[kw * 5 + o2];
                    #pragma unroll
                    for (int o2 = 0; o2 < 5; ++o2) {
                        #pragma unroll
                        for (int p = 0; p < 4; ++p)
                            FMA2(acc[o2][p], w[o2], rr[kw + p], acc[o2][p]);
                    }
                }
            }
        }

        // ---- store: two float4 per o-pair ----
        #pragma unroll
        for (int o2 = 0; o2 < 5; ++o2) {
            float lo0, hi0, lo1, hi1, lo2, hi2, lo3, hi3;
            UNPACK2(lo0, hi0, acc[o2][0]);
            UNPACK2(lo1, hi1, acc[o2][1]);
            UNPACK2(lo2, hi2, acc[o2][2]);
            UNPACK2(lo3, hi3, acc[o2][3]);
            float4 va = make_float4(lo0, lo1, lo2, lo3);
            float4 vb = make_float4(hi0, hi1, hi2, hi3);
            *(float4*)(outp + ((2 * o2) * 10 + d) * (HW * HW))     = va;
            *(float4*)(outp + ((2 * o2 + 1) * 10 + d) * (HW * HW)) = vb;
        }

        // orders: compute(job) before ws/xs overwrite of next job
        __syncthreads();
    }
}

extern "C" void kernel_launch(void* const* d_in, const int* in_sizes, int n_in,
                              void* d_out, int out_size) {
    const float* x    = (const float*)d_in[0];
    const float* W    = (const float*)d_in[1];
    const float* bias = (const float*)d_in[2];
    float* out = (float*)d_out;

    repack_kernel<<<49, 256>>>(W);

    const size_t smem_bytes = SMEM_FLOATS * sizeof(float);
    cudaFuncSetAttribute(conv_main, cudaFuncAttributeMaxDynamicSharedMemorySize,
                         (int)smem_bytes);

    conv_main<<<NCTAS, 128, smem_bytes>>>(x, bias, out);
}